// round 3
// baseline (speedup 1.0000x reference)
#include <cuda_runtime.h>
#include <cstdint>

#define D_MODEL   768
#define N_FEAT    32768
#define BATCH     1024
#define TOPK      64
#define AUXK      128
#define DEAD_AFTER 1000
#define AUX_COEFF 0.03125f

// ---------------- scratch (device globals; no allocations) ----------------
__device__ float g_xc[BATCH * D_MODEL];                 // (x_normed - b_post + b_pre)
__device__ float g_enc[(size_t)BATCH * N_FEAT];         // encodings, 134 MB
__device__ float g_wAll[BATCH * TOPK];
__device__ int   g_iAll[BATCH * TOPK];
__device__ float g_wDead[BATCH * AUXK];
__device__ int   g_iDead[BATCH * AUXK];
__device__ float g_rowNum[BATCH];
__device__ float g_rowDen[BATCH];
__device__ int   g_deadAny;

// ---------------- helpers ----------------
__device__ __forceinline__ unsigned f2key(float f) {
    unsigned u = __float_as_uint(f);
    return (u & 0x80000000u) ? ~u : (u | 0x80000000u);   // order-preserving uint
}
__device__ __forceinline__ float key2f(unsigned k) {
    unsigned u = (k & 0x80000000u) ? (k ^ 0x80000000u) : ~k;
    return __uint_as_float(u);
}

// ---------------- kernel 0: input prep ----------------
__global__ void prep_kernel(const float* __restrict__ x,
                            const float* __restrict__ b_pre,
                            const float* __restrict__ b_post,
                            const float* __restrict__ avg) {
    int i = blockIdx.x * 256 + threadIdx.x;
    if (i < BATCH * D_MODEL) {
        float s = sqrtf((float)D_MODEL) / avg[0];
        int d = i % D_MODEL;
        g_xc[i] = x[i] * s - b_post[d] + b_pre[d];
    }
}

__global__ void deadany_kernel(const int* __restrict__ act) {
    __shared__ int f;
    if (threadIdx.x == 0) f = 0;
    __syncthreads();
    int loc = 0;
    for (int i = threadIdx.x; i < N_FEAT; i += 256)
        if (act[i] > DEAD_AFTER) loc = 1;
    if (loc) atomicOr(&f, 1);
    __syncthreads();
    if (threadIdx.x == 0) g_deadAny = f;
}

// ---------------- kernel 1: SGEMM  enc = xc @ W_enc ----------------
// A=g_xc [1024,768] row-major, B=W_enc [768,32768] row-major, C=g_enc [1024,32768]
// 128x128 tile, BK=8, 256 threads, 8x8 microtile.
__global__ __launch_bounds__(256) void sgemm_kernel(const float* __restrict__ B) {
    const int N = N_FEAT, Kd = D_MODEL;
    __shared__ float As[8][128];
    __shared__ float Bs[8][128];
    int tid = threadIdx.x;
    int bm = blockIdx.x;        // 0..7   (M tiles)
    int bn = blockIdx.y;        // 0..255 (N tiles)

    const float* Ablk = g_xc + (size_t)bm * 128 * Kd;
    const float* Bblk = B + (size_t)bn * 128;

    int arow = tid >> 1;            // 0..127
    int acol = (tid & 1) * 4;       // 0 or 4
    int brow = tid >> 5;            // 0..7
    int bcol = (tid & 31) * 4;      // 0..124
    int tr  = (tid >> 4) * 8;       // micro-tile row base
    int tcc = (tid & 15) * 8;       // micro-tile col base

    float acc[8][8];
#pragma unroll
    for (int i = 0; i < 8; i++)
#pragma unroll
        for (int j = 0; j < 8; j++) acc[i][j] = 0.f;

    for (int k0 = 0; k0 < Kd; k0 += 8) {
        float4 av = *(const float4*)(Ablk + (size_t)arow * Kd + k0 + acol);
        As[acol + 0][arow] = av.x;
        As[acol + 1][arow] = av.y;
        As[acol + 2][arow] = av.z;
        As[acol + 3][arow] = av.w;
        *(float4*)(&Bs[brow][bcol]) =
            *(const float4*)(Bblk + (size_t)(k0 + brow) * N + bcol);
        __syncthreads();
#pragma unroll
        for (int kk = 0; kk < 8; kk++) {
            float ar[8], br[8];
#pragma unroll
            for (int i = 0; i < 8; i++) ar[i] = As[kk][tr + i];
#pragma unroll
            for (int j = 0; j < 8; j++) br[j] = Bs[kk][tcc + j];
#pragma unroll
            for (int i = 0; i < 8; i++)
#pragma unroll
                for (int j = 0; j < 8; j++) acc[i][j] += ar[i] * br[j];
        }
        __syncthreads();
    }

    float* Cb = g_enc + (size_t)(bm * 128) * N + (size_t)bn * 128;
#pragma unroll
    for (int i = 0; i < 8; i++) {
        float4 v0 = make_float4(acc[i][0], acc[i][1], acc[i][2], acc[i][3]);
        float4 v1 = make_float4(acc[i][4], acc[i][5], acc[i][6], acc[i][7]);
        *(float4*)(Cb + (size_t)(tr + i) * N + tcc)     = v0;
        *(float4*)(Cb + (size_t)(tr + i) * N + tcc + 4) = v1;
    }
}

// ---------------- kernel 2: exact per-row top-K (optionally masked to dead) ----
// NOTE: output arrays are selected INSIDE the kernel (device-side symbol refs).
// Passing __device__ globals as host-side kernel args is invalid (host shadow
// address) — that was the round-1/2 failure.
__global__ __launch_bounds__(256) void topk_kernel(const int* __restrict__ act,
                                                   int useMask) {
    __shared__ unsigned shKey[4096];       // histogram, then in-bin keys
    __shared__ unsigned shIdx[4096];
    __shared__ int scanD[256], scanB[256];
    __shared__ int s_binT, s_above, s_m;
    __shared__ unsigned long long s_red[256];

    int tid = threadIdx.x, row = blockIdx.x;
    const float* e = g_enc + (size_t)row * N_FEAT;

    const int Ksel = useMask ? AUXK : TOPK;
    float* outW = useMask ? g_wDead : g_wAll;
    int*   outI = useMask ? g_iDead : g_iAll;

    for (int i = tid; i < 4096; i += 256) shKey[i] = 0;
    __syncthreads();
    for (int i = tid; i < N_FEAT; i += 256) {
        if (!useMask || act[i] > DEAD_AFTER)
            atomicAdd(&shKey[f2key(e[i]) >> 20], 1u);
    }
    __syncthreads();
    if (tid == 0) {
        int cum = 0, binT = -1, above = 0;
        for (int b = 4095; b >= 0; --b) {
            int c = (int)shKey[b];
            if (cum + c >= Ksel) { binT = b; above = cum; break; }
            cum += c;
        }
        if (binT < 0) above = cum;      // fewer than Ksel eligible: take all
        s_binT = binT; s_above = above;
    }
    __syncthreads();
    int binT = s_binT;

    // deterministic slot assignment: count, prefix, emit
    int cD = 0, cB = 0;
    for (int i = tid; i < N_FEAT; i += 256) {
        if (!useMask || act[i] > DEAD_AFTER) {
            int b = (int)(f2key(e[i]) >> 20);
            if (binT < 0 || b > binT) cD++;
            else if (b == binT) cB++;
        }
    }
    scanD[tid] = cD; scanB[tid] = cB;
    __syncthreads();
    if (tid == 0) {
        int aD = 0, aB = 0;
        for (int t = 0; t < 256; t++) {
            int d = scanD[t]; scanD[t] = aD; aD += d;
            int b = scanB[t]; scanB[t] = aB; aB += b;
        }
        s_m = aB;
    }
    __syncthreads();
    int oD = scanD[tid], oB = scanB[tid];
    for (int i = tid; i < N_FEAT; i += 256) {
        if (!useMask || act[i] > DEAD_AFTER) {
            float v = e[i];
            unsigned u = f2key(v);
            int b = (int)(u >> 20);
            if (binT < 0 || b > binT) {
                outW[row * Ksel + oD] = v;
                outI[row * Ksel + oD] = i;
                oD++;
            } else if (b == binT) {
                if (oB < 4096) { shKey[oB] = u; shIdx[oB] = i; }
                oB++;
            }
        }
    }
    __syncthreads();

    int above = s_above;
    int m = s_m; if (m > 4096) m = 4096;
    int need = Ksel - above;
    int take = need < m ? need : m;
    for (int t = 0; t < take; t++) {
        unsigned long long best = 0;
        for (int i = tid; i < m; i += 256) {
            if (shKey[i] != 0) {
                unsigned long long p =
                    ((unsigned long long)shKey[i] << 32) |
                    (unsigned)(0xFFFFFFFFu - shIdx[i]);   // max key, then min index
                if (p > best) best = p;
            }
        }
        s_red[tid] = best;
        __syncthreads();
        for (int s = 128; s > 0; s >>= 1) {
            if (tid < s && s_red[tid + s] > s_red[tid]) s_red[tid] = s_red[tid + s];
            __syncthreads();
        }
        unsigned long long p = s_red[0];
        unsigned key = (unsigned)(p >> 32);
        unsigned idx = 0xFFFFFFFFu - (unsigned)p;
        if (tid == 0) {
            outW[row * Ksel + above + t] = key2f(key);
            outI[row * Ksel + above + t] = (int)idx;
        }
        for (int i = tid; i < m; i += 256)
            if (shKey[i] == key && shIdx[i] == idx) shKey[i] = 0;
        __syncthreads();
    }
    // pad (fewer than Ksel eligible): weight 0 == nan_to_num(neginf=0)
    for (int t = above + take + tid; t < Ksel; t += 256) {
        outW[row * Ksel + t] = 0.f;
        outI[row * Ksel + t] = 0;
    }
}

// ---------------- kernel 3: sparse decode + losses + output ----------------
__global__ __launch_bounds__(256) void decode_kernel(const float* __restrict__ x,
                                                     const float* __restrict__ Wdec,
                                                     const float* __restrict__ b_post,
                                                     const float* __restrict__ avg,
                                                     float* __restrict__ out,
                                                     int writeLoss) {
    int row = blockIdx.x, tid = threadIdx.x;
    __shared__ float sw[TOPK];  __shared__ int si[TOPK];
    __shared__ float swd[AUXK]; __shared__ int sid[AUXK];
    __shared__ float sred[256];

    if (tid < TOPK) { sw[tid] = g_wAll[row * TOPK + tid]; si[tid] = g_iAll[row * TOPK + tid]; }
    if (tid < AUXK) { swd[tid] = g_wDead[row * AUXK + tid]; sid[tid] = g_iDead[row * AUXK + tid]; }
    __syncthreads();

    float tgt = sqrtf((float)D_MODEL);
    float an  = avg[0];
    float sN = tgt / an;   // x -> x_normed
    float sD = an / tgt;   // y_normed -> y

    int d0 = tid, d1 = tid + 256, d2 = tid + 512;
    float y0 = 0.f, y1 = 0.f, y2 = 0.f;
    float a0 = 0.f, a1 = 0.f, a2 = 0.f;
#pragma unroll 4
    for (int k = 0; k < TOPK; k++) {
        const float* R = Wdec + (size_t)si[k] * D_MODEL;
        float w = sw[k];
        y0 += w * R[d0]; y1 += w * R[d1]; y2 += w * R[d2];
    }
#pragma unroll 4
    for (int k = 0; k < AUXK; k++) {
        const float* R = Wdec + (size_t)sid[k] * D_MODEL;
        float w = swd[k];
        a0 += w * R[d0]; a1 += w * R[d1]; a2 += w * R[d2];
    }

    float rec = 0.f, den = 0.f, aux = 0.f;
    {
        float xn = x[(size_t)row * D_MODEL + d0] * sN;
        float yn = y0 + b_post[d0];
        float df = xn - yn; rec += df * df; den += xn * xn;
        float t2 = (yn - xn) - a0; aux += t2 * t2;
        out[(size_t)row * D_MODEL + d0] = yn * sD;
    }
    {
        float xn = x[(size_t)row * D_MODEL + d1] * sN;
        float yn = y1 + b_post[d1];
        float df = xn - yn; rec += df * df; den += xn * xn;
        float t2 = (yn - xn) - a1; aux += t2 * t2;
        out[(size_t)row * D_MODEL + d1] = yn * sD;
    }
    {
        float xn = x[(size_t)row * D_MODEL + d2] * sN;
        float yn = y2 + b_post[d2];
        float df = xn - yn; rec += df * df; den += xn * xn;
        float t2 = (yn - xn) - a2; aux += t2 * t2;
        out[(size_t)row * D_MODEL + d2] = yn * sD;
    }

    // deterministic tree reductions
    sred[tid] = rec; __syncthreads();
    for (int s = 128; s > 0; s >>= 1) { if (tid < s) sred[tid] += sred[tid + s]; __syncthreads(); }
    float recTot = sred[0]; __syncthreads();
    sred[tid] = den; __syncthreads();
    for (int s = 128; s > 0; s >>= 1) { if (tid < s) sred[tid] += sred[tid + s]; __syncthreads(); }
    float denTot = sred[0]; __syncthreads();
    sred[tid] = aux; __syncthreads();
    for (int s = 128; s > 0; s >>= 1) { if (tid < s) sred[tid] += sred[tid + s]; __syncthreads(); }
    float auxTot = sred[0];

    if (tid == 0) {
        float lrec = recTot / (float)D_MODEL;
        float laux = g_deadAny ? (auxTot / (float)D_MODEL) : 0.f;
        if (writeLoss)
            out[(size_t)BATCH * D_MODEL + row] = lrec + AUX_COEFF * laux;
        g_rowNum[row] = recTot;
        g_rowDen[row] = denTot;
    }
}

// ---------------- kernel 4: fvu ----------------
__global__ __launch_bounds__(256) void fvu_kernel(float* __restrict__ out, int fvuIdx) {
    __shared__ float sn[256], sd[256];
    int tid = threadIdx.x;
    float n = 0.f, d = 0.f;
    for (int i = tid; i < BATCH; i += 256) { n += g_rowNum[i]; d += g_rowDen[i]; }
    sn[tid] = n; sd[tid] = d;
    __syncthreads();
    for (int s = 128; s > 0; s >>= 1) {
        if (tid < s) { sn[tid] += sn[tid + s]; sd[tid] += sd[tid + s]; }
        __syncthreads();
    }
    if (tid == 0 && fvuIdx >= 0) out[fvuIdx] = sn[0] / sd[0];
}

// ---------------- launcher ----------------
extern "C" void kernel_launch(void* const* d_in, const int* in_sizes, int n_in,
                              void* d_out, int out_size) {
    // Robust input mapping by element count (handles any metadata ordering;
    // same-size pairs keep their relative order).
    const float *x = 0, *W_enc = 0, *W_dec = 0, *b_pre = 0, *b_post = 0, *avg = 0;
    const int* act = 0;
    int nBig = 0, nBias = 0;
    for (int i = 0; i < n_in; i++) {
        long s = in_sizes[i];
        if (s == (long)D_MODEL * N_FEAT) {            // 25165824: W_enc then W_dec
            if (nBig++ == 0) W_enc = (const float*)d_in[i];
            else             W_dec = (const float*)d_in[i];
        } else if (s == (long)BATCH * D_MODEL) {      // 786432: x
            x = (const float*)d_in[i];
        } else if (s == D_MODEL) {                    // 768: b_pre then b_post
            if (nBias++ == 0) b_pre = (const float*)d_in[i];
            else              b_post = (const float*)d_in[i];
        } else if (s == 1) {                          // avg_norm
            avg = (const float*)d_in[i];
        } else if (s == N_FEAT) {                     // 32768: activated_in (int32)
            act = (const int*)d_in[i];
        }
    }
    float* out = (float*)d_out;

    // Output layout (gated by out_size to avoid OOB whatever the harness allocates):
    //   y    at [0, 786432)
    //   loss at [786432, 787456)   if present
    //   fvu  at 787456             if present
    int writeLoss = (out_size >= BATCH * D_MODEL + BATCH) ? 1 : 0;
    int fvuIdx = (out_size >= BATCH * D_MODEL + BATCH + 1) ? (BATCH * D_MODEL + BATCH) : -1;

    prep_kernel<<<(BATCH * D_MODEL + 255) / 256, 256>>>(x, b_pre, b_post, avg);
    deadany_kernel<<<1, 256>>>(act);

    dim3 gg(8, 256);
    sgemm_kernel<<<gg, 256>>>(W_enc);

    topk_kernel<<<BATCH, 256>>>(act, 0);   // TOPK=64  -> g_wAll/g_iAll
    topk_kernel<<<BATCH, 256>>>(act, 1);   // AUXK=128 -> g_wDead/g_iDead

    decode_kernel<<<BATCH, 256>>>(x, W_dec, b_post, avg, out, writeLoss);
    if (fvuIdx >= 0) fvu_kernel<<<1, 256>>>(out, fvuIdx);
}

// round 5
// speedup vs baseline: 1.8719x; 1.8719x over previous
#include <cuda_runtime.h>
#include <cuda_bf16.h>
#include <cstdint>

#define D_MODEL   768
#define N_FEAT    32768
#define BATCH     1024
#define TOPK      64
#define AUXK      128
#define DEAD_AFTER 1000
#define AUX_COEFF 0.03125f

#define NEED_A   88      // TOPK + 24 margin
#define NEED_D   152     // AUXK + 24 margin
#define CAND_CAP 768
#define LISTCAP  1280

// ---------------- scratch (device globals; no allocations) ----------------
__device__ float          g_xc[BATCH * D_MODEL];            // exact fp32 (x_normed - b_post + b_pre)
__device__ __nv_bfloat16  g_xh[BATCH * D_MODEL];            // bf16 of xc
__device__ __nv_bfloat16  g_wh[(size_t)D_MODEL * N_FEAT];   // bf16 W_enc, [K,N] layout
__device__ float          g_wT[(size_t)N_FEAT * D_MODEL];   // fp32 W_enc^T, [N,K] for rescore
__device__ float          g_enc[(size_t)BATCH * N_FEAT];    // approx encodings
__device__ int            g_candIdxA[BATCH * CAND_CAP];
__device__ int            g_candIdxD[BATCH * CAND_CAP];
__device__ float          g_candValA[BATCH * CAND_CAP];
__device__ float          g_candValD[BATCH * CAND_CAP];
__device__ int            g_candCntA[BATCH];
__device__ int            g_candCntD[BATCH];
__device__ float g_wAll[BATCH * TOPK];
__device__ int   g_iAll[BATCH * TOPK];
__device__ float g_wDead[BATCH * AUXK];
__device__ int   g_iDead[BATCH * AUXK];
__device__ float g_rowNum[BATCH];
__device__ float g_rowDen[BATCH];
__device__ int   g_deadAny;

// ---------------- helpers ----------------
__device__ __forceinline__ unsigned f2key(float f) {
    unsigned u = __float_as_uint(f);
    return (u & 0x80000000u) ? ~u : (u | 0x80000000u);   // order-preserving uint
}
__device__ __forceinline__ float key2f(unsigned k) {
    unsigned u = (k & 0x80000000u) ? (k ^ 0x80000000u) : ~k;
    return __uint_as_float(u);
}

// ---------------- kernel 0: input prep (fp32 xc + bf16 copy) ----------------
__global__ void prep_kernel(const float* __restrict__ x,
                            const float* __restrict__ b_pre,
                            const float* __restrict__ b_post,
                            const float* __restrict__ avg) {
    int i = blockIdx.x * 256 + threadIdx.x;
    if (i < BATCH * D_MODEL) {
        float s = sqrtf((float)D_MODEL) / avg[0];
        int d = i % D_MODEL;
        float v = x[i] * s - b_post[d] + b_pre[d];
        g_xc[i] = v;
        g_xh[i] = __float2bfloat16(v);
    }
}

__global__ void deadany_kernel(const int* __restrict__ act) {
    __shared__ int f;
    if (threadIdx.x == 0) f = 0;
    __syncthreads();
    int loc = 0;
    for (int i = threadIdx.x; i < N_FEAT; i += 256)
        if (act[i] > DEAD_AFTER) loc = 1;
    if (loc) atomicOr(&f, 1);
    __syncthreads();
    if (threadIdx.x == 0) g_deadAny = f;
}

// ---------------- kernel 1: W_enc split (bf16) + transpose (fp32) ----------
__global__ __launch_bounds__(256) void wsplit_kernel(const float* __restrict__ W) {
    __shared__ float tile[32][33];
    int tx = threadIdx.x & 31, ty = threadIdx.x >> 5;   // 8 row-groups
    int n0 = blockIdx.x * 32;       // 1024 tiles along N
    int k0 = blockIdx.y * 32;       // 24 tiles along K
#pragma unroll
    for (int r = ty; r < 32; r += 8) {
        float v = W[(size_t)(k0 + r) * N_FEAT + n0 + tx];
        tile[r][tx] = v;
        g_wh[(size_t)(k0 + r) * N_FEAT + n0 + tx] = __float2bfloat16(v);
    }
    __syncthreads();
#pragma unroll
    for (int r = ty; r < 32; r += 8) {
        g_wT[(size_t)(n0 + r) * D_MODEL + k0 + tx] = tile[tx][r];
    }
}

// ---------------- kernel 2: bf16 GEMM (mma.sync m16n8k16) ------------------
// enc[1024,32768] = xh[1024,768] @ wh[768,32768], fp32 accum.
// CTA tile 128x128, 8 warps (4M x 2N), warp tile 32x64, BK=32.
__global__ __launch_bounds__(256) void gemm_kernel() {
    __shared__ __nv_bfloat16 As[2][128][40];     // [m][k], padded
    __shared__ __nv_bfloat16 Bs[2][32][136];     // [k][n], padded
    int tid = threadIdx.x;
    int warp = tid >> 5, lane = tid & 31;
    int mbase = (warp >> 1) * 32, nbase = (warp & 1) * 64;
    int bn = blockIdx.x, bm = blockIdx.y;

    const __nv_bfloat16* Ag = g_xh + (size_t)bm * 128 * D_MODEL;
    const __nv_bfloat16* Bg = g_wh + (size_t)bn * 128;

    int am0 = tid >> 2, ak = (tid & 3) * 8;      // A loader: rows am0, am0+64 (8 bf16 each)
    int bk = tid >> 3, bn0 = (tid & 7) * 16;     // B loader: 16 bf16 = TWO uint4 per thread

    float acc[2][8][4];
#pragma unroll
    for (int mt = 0; mt < 2; mt++)
#pragma unroll
        for (int nt = 0; nt < 8; nt++)
#pragma unroll
            for (int q = 0; q < 4; q++) acc[mt][nt][q] = 0.f;

    uint4 pa0 = *(const uint4*)(Ag + (size_t)am0 * D_MODEL + ak);
    uint4 pa1 = *(const uint4*)(Ag + (size_t)(am0 + 64) * D_MODEL + ak);
    uint4 pb0 = *(const uint4*)(Bg + (size_t)bk * N_FEAT + bn0);
    uint4 pb1 = *(const uint4*)(Bg + (size_t)bk * N_FEAT + bn0 + 8);
    *(uint4*)(&As[0][am0][ak])      = pa0;
    *(uint4*)(&As[0][am0 + 64][ak]) = pa1;
    *(uint4*)(&Bs[0][bk][bn0])      = pb0;
    *(uint4*)(&Bs[0][bk][bn0 + 8])  = pb1;
    __syncthreads();

    const int NSLAB = D_MODEL / 32;   // 24
    for (int s = 0; s < NSLAB; s++) {
        int cur = s & 1;
        if (s + 1 < NSLAB) {
            int k0 = (s + 1) * 32;
            pa0 = *(const uint4*)(Ag + (size_t)am0 * D_MODEL + k0 + ak);
            pa1 = *(const uint4*)(Ag + (size_t)(am0 + 64) * D_MODEL + k0 + ak);
            pb0 = *(const uint4*)(Bg + (size_t)(k0 + bk) * N_FEAT + bn0);
            pb1 = *(const uint4*)(Bg + (size_t)(k0 + bk) * N_FEAT + bn0 + 8);
        }
        int r = lane >> 2, c = (lane & 3) * 2;
#pragma unroll
        for (int kk = 0; kk < 32; kk += 16) {
            unsigned a[2][4];
#pragma unroll
            for (int mt = 0; mt < 2; mt++) {
                const __nv_bfloat16* ap = &As[cur][mbase + mt * 16 + r][kk + c];
                a[mt][0] = *(const unsigned*)(ap);
                a[mt][1] = *(const unsigned*)(ap + 8 * 40);
                a[mt][2] = *(const unsigned*)(ap + 8);
                a[mt][3] = *(const unsigned*)(ap + 8 * 40 + 8);
            }
            int kb = kk + (lane & 3) * 2, nb2 = lane >> 2;
            const unsigned short* bp = (const unsigned short*)&Bs[cur][0][0];
#pragma unroll
            for (int nt = 0; nt < 8; nt++) {
                int n = nbase + nt * 8 + nb2;
                unsigned b0 = (unsigned)bp[kb * 136 + n] | ((unsigned)bp[(kb + 1) * 136 + n] << 16);
                unsigned b1 = (unsigned)bp[(kb + 8) * 136 + n] | ((unsigned)bp[(kb + 9) * 136 + n] << 16);
#pragma unroll
                for (int mt = 0; mt < 2; mt++) {
                    asm volatile(
                        "mma.sync.aligned.m16n8k16.row.col.f32.bf16.bf16.f32 "
                        "{%0,%1,%2,%3}, {%4,%5,%6,%7}, {%8,%9}, {%0,%1,%2,%3};"
                        : "+f"(acc[mt][nt][0]), "+f"(acc[mt][nt][1]),
                          "+f"(acc[mt][nt][2]), "+f"(acc[mt][nt][3])
                        : "r"(a[mt][0]), "r"(a[mt][1]), "r"(a[mt][2]), "r"(a[mt][3]),
                          "r"(b0), "r"(b1));
                }
            }
        }
        __syncthreads();
        if (s + 1 < NSLAB) {
            int nxt = cur ^ 1;
            *(uint4*)(&As[nxt][am0][ak])      = pa0;
            *(uint4*)(&As[nxt][am0 + 64][ak]) = pa1;
            *(uint4*)(&Bs[nxt][bk][bn0])      = pb0;
            *(uint4*)(&Bs[nxt][bk][bn0 + 8])  = pb1;
            __syncthreads();
        }
    }

    int r = lane >> 2, cn = (lane & 3) * 2;
    float* C = g_enc + (size_t)(bm * 128) * N_FEAT + bn * 128;
#pragma unroll
    for (int mt = 0; mt < 2; mt++)
#pragma unroll
        for (int nt = 0; nt < 8; nt++) {
            int m0 = mbase + mt * 16 + r;
            int n0 = nbase + nt * 8 + cn;
            *(float2*)&C[(size_t)m0 * N_FEAT + n0]       = make_float2(acc[mt][nt][0], acc[mt][nt][1]);
            *(float2*)&C[(size_t)(m0 + 8) * N_FEAT + n0] = make_float2(acc[mt][nt][2], acc[mt][nt][3]);
        }
}

// ---------------- kernel 3: candidate extraction (both selections) ---------
// 12-bit histogram -> threshold bin -> emit above-bin + refine in-bin by next
// 12 key bits. Candidate SET is deterministic; buffer order need not be.
__global__ __launch_bounds__(256) void cand_kernel(const int* __restrict__ act) {
    __shared__ unsigned histAD[4096];              // packed: A low16, D high16
    __shared__ unsigned listKeyA[LISTCAP]; __shared__ int listIdxA[LISTCAP];
    __shared__ unsigned listKeyD[LISTCAP]; __shared__ int listIdxD[LISTCAP];
    __shared__ int chs[256];
    __shared__ int s_binA, s_aboveA, s_binD, s_aboveD;
    __shared__ int s_cntA, s_cntD, s_mA, s_mD, s_subA, s_subD;

    int tid = threadIdx.x, row = blockIdx.x;
    const float4* e4 = (const float4*)(g_enc + (size_t)row * N_FEAT);
    const int4* a4 = (const int4*)act;

    for (int i = tid; i < 4096; i += 256) histAD[i] = 0;
    if (tid == 0) { s_cntA = 0; s_cntD = 0; s_mA = 0; s_mD = 0; }
    __syncthreads();

    // pass 1: packed histogram
    for (int i = tid; i < N_FEAT / 4; i += 256) {
        float4 v = e4[i]; int4 av = a4[i];
        atomicAdd(&histAD[f2key(v.x) >> 20], 1u + ((av.x > DEAD_AFTER) ? 0x10000u : 0u));
        atomicAdd(&histAD[f2key(v.y) >> 20], 1u + ((av.y > DEAD_AFTER) ? 0x10000u : 0u));
        atomicAdd(&histAD[f2key(v.z) >> 20], 1u + ((av.z > DEAD_AFTER) ? 0x10000u : 0u));
        atomicAdd(&histAD[f2key(v.w) >> 20], 1u + ((av.w > DEAD_AFTER) ? 0x10000u : 0u));
    }
    __syncthreads();

    // thresholds: A (low halves)
    {
        int c0 = tid * 16; unsigned sA = 0;
#pragma unroll
        for (int j = 0; j < 16; j++) sA += histAD[c0 + j] & 0xFFFFu;
        chs[tid] = (int)sA;
        __syncthreads();
        if (tid == 0) {
            int cum = 0, bin = -1, above = 0;
            for (int ch = 255; ch >= 0; ch--) {
                if (cum + chs[ch] >= NEED_A) {
                    for (int b = ch * 16 + 15; b >= ch * 16; b--) {
                        int c = (int)(histAD[b] & 0xFFFFu);
                        if (cum + c >= NEED_A) { bin = b; above = cum; break; }
                        cum += c;
                    }
                    break;
                }
                cum += chs[ch];
            }
            if (bin < 0) above = cum;
            s_binA = bin; s_aboveA = above;
        }
        __syncthreads();
    }
    // thresholds: D (high halves)
    {
        int c0 = tid * 16; unsigned sD = 0;
#pragma unroll
        for (int j = 0; j < 16; j++) sD += histAD[c0 + j] >> 16;
        chs[tid] = (int)sD;
        __syncthreads();
        if (tid == 0) {
            int cum = 0, bin = -1, above = 0;
            for (int ch = 255; ch >= 0; ch--) {
                if (cum + chs[ch] >= NEED_D) {
                    for (int b = ch * 16 + 15; b >= ch * 16; b--) {
                        int c = (int)(histAD[b] >> 16);
                        if (cum + c >= NEED_D) { bin = b; above = cum; break; }
                        cum += c;
                    }
                    break;
                }
                cum += chs[ch];
            }
            if (bin < 0) above = cum;
            s_binD = bin; s_aboveD = above;
        }
        __syncthreads();
    }

    int binA = s_binA, binD = s_binD;

    // pass 2: emit above-bin directly; in-bin to smem lists
    for (int i = tid; i < N_FEAT / 4; i += 256) {
        float4 v = e4[i]; int4 av = a4[i];
        float vv[4] = {v.x, v.y, v.z, v.w};
        int aa[4] = {av.x, av.y, av.z, av.w};
#pragma unroll
        for (int j = 0; j < 4; j++) {
            int idx = i * 4 + j;
            unsigned key = f2key(vv[j]);
            int b = (int)(key >> 20);
            if (binA < 0 || b > binA) {
                int p = atomicAdd(&s_cntA, 1);
                if (p < CAND_CAP) g_candIdxA[row * CAND_CAP + p] = idx;
            } else if (b == binA) {
                int p = atomicAdd(&s_mA, 1);
                if (p < LISTCAP) { listKeyA[p] = key; listIdxA[p] = idx; }
            }
            if (aa[j] > DEAD_AFTER) {
                if (binD < 0 || b > binD) {
                    int p = atomicAdd(&s_cntD, 1);
                    if (p < CAND_CAP) g_candIdxD[row * CAND_CAP + p] = idx;
                } else if (b == binD) {
                    int p = atomicAdd(&s_mD, 1);
                    if (p < LISTCAP) { listKeyD[p] = key; listIdxD[p] = idx; }
                }
            }
        }
    }
    __syncthreads();

    // sub-bin refinement (next 12 key bits), packed hist again
    for (int i = tid; i < 4096; i += 256) histAD[i] = 0;
    __syncthreads();
    int mA = min(s_mA, LISTCAP), mD = min(s_mD, LISTCAP);
    for (int i = tid; i < mA; i += 256) atomicAdd(&histAD[(listKeyA[i] >> 8) & 0xFFF], 1u);
    for (int i = tid; i < mD; i += 256) atomicAdd(&histAD[(listKeyD[i] >> 8) & 0xFFF], 0x10000u);
    __syncthreads();
    if (tid == 0) {
        int need = NEED_A - s_aboveA, cum = 0, sub = 0;
        if (binA >= 0) {
            for (int b = 4095; b >= 0; b--) {
                cum += (int)(histAD[b] & 0xFFFFu);
                if (cum >= need) { sub = b; break; }
            }
        }
        s_subA = sub;
        need = NEED_D - s_aboveD; cum = 0; sub = 0;
        if (binD >= 0) {
            for (int b = 4095; b >= 0; b--) {
                cum += (int)(histAD[b] >> 16);
                if (cum >= need) { sub = b; break; }
            }
        }
        s_subD = sub;
    }
    __syncthreads();
    int subA = s_subA, subD = s_subD;
    for (int i = tid; i < mA; i += 256)
        if ((int)((listKeyA[i] >> 8) & 0xFFF) >= subA) {
            int p = atomicAdd(&s_cntA, 1);
            if (p < CAND_CAP) g_candIdxA[row * CAND_CAP + p] = listIdxA[i];
        }
    for (int i = tid; i < mD; i += 256)
        if ((int)((listKeyD[i] >> 8) & 0xFFF) >= subD) {
            int p = atomicAdd(&s_cntD, 1);
            if (p < CAND_CAP) g_candIdxD[row * CAND_CAP + p] = listIdxD[i];
        }
    __syncthreads();
    if (tid == 0) {
        g_candCntA[row] = min(s_cntA, CAND_CAP);
        g_candCntD[row] = min(s_cntD, CAND_CAP);
    }
}

// ---------------- kernel 4: exact fp32 rescore of candidates ----------------
__global__ __launch_bounds__(256) void rescore_kernel() {
    __shared__ float xs[D_MODEL];
    int row = blockIdx.x, tid = threadIdx.x;
    for (int i = tid; i < D_MODEL; i += 256) xs[i] = g_xc[row * D_MODEL + i];
    __syncthreads();
    int cA = g_candCntA[row], cD = g_candCntD[row];
    int tot = cA + cD;
    const float4* x4 = (const float4*)xs;
    for (int t = tid; t < tot; t += 256) {
        int idx = (t < cA) ? g_candIdxA[row * CAND_CAP + t]
                           : g_candIdxD[row * CAND_CAP + (t - cA)];
        const float4* w4 = (const float4*)(g_wT + (size_t)idx * D_MODEL);
        float acc = 0.f;
#pragma unroll 4
        for (int k = 0; k < D_MODEL / 4; k++) {
            float4 w = w4[k], xv = x4[k];
            acc += xv.x * w.x;
            acc += xv.y * w.y;
            acc += xv.z * w.z;
            acc += xv.w * w.w;
        }
        if (t < cA) g_candValA[row * CAND_CAP + t] = acc;
        else        g_candValD[row * CAND_CAP + (t - cA)] = acc;
    }
}

// ---------------- kernel 5: final exact top-K among candidates --------------
__global__ __launch_bounds__(256) void select_kernel() {
    __shared__ unsigned long long sv[CAND_CAP];
    __shared__ unsigned long long wred[8];
    int row = blockIdx.x, tid = threadIdx.x;
    int isD = blockIdx.y;
    int cnt  = isD ? g_candCntD[row] : g_candCntA[row];
    int Ksel = isD ? AUXK : TOPK;
    const float* vals = isD ? &g_candValD[row * CAND_CAP] : &g_candValA[row * CAND_CAP];
    const int*   idxs = isD ? &g_candIdxD[row * CAND_CAP] : &g_candIdxA[row * CAND_CAP];
    float* outW = isD ? &g_wDead[row * AUXK] : &g_wAll[row * TOPK];
    int*   outI = isD ? &g_iDead[row * AUXK] : &g_iAll[row * TOPK];

    for (int i = tid; i < cnt; i += 256)
        sv[i] = ((unsigned long long)f2key(vals[i]) << 32) | (unsigned)(~(unsigned)idxs[i]);
    __syncthreads();

    int take = min(Ksel, cnt);
    for (int t = 0; t < take; t++) {
        unsigned long long best = 0;
        for (int i = tid; i < cnt; i += 256) if (sv[i] > best) best = sv[i];
#pragma unroll
        for (int o = 16; o; o >>= 1) {
            unsigned long long other = __shfl_xor_sync(0xffffffffu, best, o);
            if (other > best) best = other;
        }
        if ((tid & 31) == 0) wred[tid >> 5] = best;
        __syncthreads();
        if (tid < 8) {
            best = wred[tid];
#pragma unroll
            for (int o = 4; o; o >>= 1) {
                unsigned long long other = __shfl_xor_sync(0xffu, best, o);
                if (other > best) best = other;
            }
            if (tid == 0) wred[0] = best;
        }
        __syncthreads();
        unsigned long long b = wred[0];
        if (tid == 0) {
            outW[t] = key2f((unsigned)(b >> 32));
            outI[t] = (int)(~(unsigned)b);
        }
        for (int i = tid; i < cnt; i += 256) if (sv[i] == b) sv[i] = 0;
        __syncthreads();
    }
    for (int t = take + tid; t < Ksel; t += 256) { outW[t] = 0.f; outI[t] = 0; }
}

// ---------------- kernel 6: sparse decode + losses + output ----------------
__global__ __launch_bounds__(256) void decode_kernel(const float* __restrict__ x,
                                                     const float* __restrict__ Wdec,
                                                     const float* __restrict__ b_post,
                                                     const float* __restrict__ avg,
                                                     float* __restrict__ out,
                                                     int writeLoss) {
    int row = blockIdx.x, tid = threadIdx.x;
    __shared__ float sw[TOPK];  __shared__ int si[TOPK];
    __shared__ float swd[AUXK]; __shared__ int sid[AUXK];
    __shared__ float sred[256];

    if (tid < TOPK) { sw[tid] = g_wAll[row * TOPK + tid]; si[tid] = g_iAll[row * TOPK + tid]; }
    if (tid < AUXK) { swd[tid] = g_wDead[row * AUXK + tid]; sid[tid] = g_iDead[row * AUXK + tid]; }
    __syncthreads();

    float tgt = sqrtf((float)D_MODEL);
    float an  = avg[0];
    float sN = tgt / an;
    float sD = an / tgt;

    int d0 = tid, d1 = tid + 256, d2 = tid + 512;
    float y0 = 0.f, y1 = 0.f, y2 = 0.f;
    float a0 = 0.f, a1 = 0.f, a2 = 0.f;
#pragma unroll 4
    for (int k = 0; k < TOPK; k++) {
        const float* R = Wdec + (size_t)si[k] * D_MODEL;
        float w = sw[k];
        y0 += w * R[d0]; y1 += w * R[d1]; y2 += w * R[d2];
    }
#pragma unroll 4
    for (int k = 0; k < AUXK; k++) {
        const float* R = Wdec + (size_t)sid[k] * D_MODEL;
        float w = swd[k];
        a0 += w * R[d0]; a1 += w * R[d1]; a2 += w * R[d2];
    }

    float rec = 0.f, den = 0.f, aux = 0.f;
    {
        float xn = x[(size_t)row * D_MODEL + d0] * sN;
        float yn = y0 + b_post[d0];
        float df = xn - yn; rec += df * df; den += xn * xn;
        float t2 = (yn - xn) - a0; aux += t2 * t2;
        out[(size_t)row * D_MODEL + d0] = yn * sD;
    }
    {
        float xn = x[(size_t)row * D_MODEL + d1] * sN;
        float yn = y1 + b_post[d1];
        float df = xn - yn; rec += df * df; den += xn * xn;
        float t2 = (yn - xn) - a1; aux += t2 * t2;
        out[(size_t)row * D_MODEL + d1] = yn * sD;
    }
    {
        float xn = x[(size_t)row * D_MODEL + d2] * sN;
        float yn = y2 + b_post[d2];
        float df = xn - yn; rec += df * df; den += xn * xn;
        float t2 = (yn - xn) - a2; aux += t2 * t2;
        out[(size_t)row * D_MODEL + d2] = yn * sD;
    }

    sred[tid] = rec; __syncthreads();
    for (int s = 128; s > 0; s >>= 1) { if (tid < s) sred[tid] += sred[tid + s]; __syncthreads(); }
    float recTot = sred[0]; __syncthreads();
    sred[tid] = den; __syncthreads();
    for (int s = 128; s > 0; s >>= 1) { if (tid < s) sred[tid] += sred[tid + s]; __syncthreads(); }
    float denTot = sred[0]; __syncthreads();
    sred[tid] = aux; __syncthreads();
    for (int s = 128; s > 0; s >>= 1) { if (tid < s) sred[tid] += sred[tid + s]; __syncthreads(); }
    float auxTot = sred[0];

    if (tid == 0) {
        float lrec = recTot / (float)D_MODEL;
        float laux = g_deadAny ? (auxTot / (float)D_MODEL) : 0.f;
        if (writeLoss)
            out[(size_t)BATCH * D_MODEL + row] = lrec + AUX_COEFF * laux;
        g_rowNum[row] = recTot;
        g_rowDen[row] = denTot;
    }
}

// ---------------- kernel 7: fvu ----------------
__global__ __launch_bounds__(256) void fvu_kernel(float* __restrict__ out, int fvuIdx) {
    __shared__ float sn[256], sd[256];
    int tid = threadIdx.x;
    float n = 0.f, d = 0.f;
    for (int i = tid; i < BATCH; i += 256) { n += g_rowNum[i]; d += g_rowDen[i]; }
    sn[tid] = n; sd[tid] = d;
    __syncthreads();
    for (int s = 128; s > 0; s >>= 1) {
        if (tid < s) { sn[tid] += sn[tid + s]; sd[tid] += sd[tid + s]; }
        __syncthreads();
    }
    if (tid == 0 && fvuIdx >= 0) out[fvuIdx] = sn[0] / sd[0];
}

// ---------------- launcher ----------------
extern "C" void kernel_launch(void* const* d_in, const int* in_sizes, int n_in,
                              void* d_out, int out_size) {
    const float *x = 0, *W_enc = 0, *W_dec = 0, *b_pre = 0, *b_post = 0, *avg = 0;
    const int* act = 0;
    int nBig = 0, nBias = 0;
    for (int i = 0; i < n_in; i++) {
        long s = in_sizes[i];
        if (s == (long)D_MODEL * N_FEAT) {
            if (nBig++ == 0) W_enc = (const float*)d_in[i];
            else             W_dec = (const float*)d_in[i];
        } else if (s == (long)BATCH * D_MODEL) {
            x = (const float*)d_in[i];
        } else if (s == D_MODEL) {
            if (nBias++ == 0) b_pre = (const float*)d_in[i];
            else              b_post = (const float*)d_in[i];
        } else if (s == 1) {
            avg = (const float*)d_in[i];
        } else if (s == N_FEAT) {
            act = (const int*)d_in[i];
        }
    }
    float* out = (float*)d_out;

    int writeLoss = (out_size >= BATCH * D_MODEL + BATCH) ? 1 : 0;
    int fvuIdx = (out_size >= BATCH * D_MODEL + BATCH + 1) ? (BATCH * D_MODEL + BATCH) : -1;

    prep_kernel<<<(BATCH * D_MODEL + 255) / 256, 256>>>(x, b_pre, b_post, avg);
    wsplit_kernel<<<dim3(N_FEAT / 32, D_MODEL / 32), 256>>>(W_enc);
    deadany_kernel<<<1, 256>>>(act);

    gemm_kernel<<<dim3(N_FEAT / 128, BATCH / 128), 256>>>();

    cand_kernel<<<BATCH, 256>>>(act);
    rescore_kernel<<<BATCH, 256>>>();
    select_kernel<<<dim3(BATCH, 2), 256>>>();

    decode_kernel<<<BATCH, 256>>>(x, W_dec, b_post, avg, out, writeLoss);
    if (fvuIdx >= 0) fvu_kernel<<<1, 256>>>(out, fvuIdx);
}

// round 7
// speedup vs baseline: 2.2081x; 1.1796x over previous
#include <cuda_runtime.h>
#include <cuda_bf16.h>
#include <cstdint>

#define D_MODEL   768
#define N_FEAT    32768
#define BATCH     1024
#define TOPK      64
#define AUXK      128
#define DEAD_AFTER 1000
#define AUX_COEFF 0.03125f

#define NEED_A   88      // TOPK + 24 margin
#define NEED_D   152     // AUXK + 24 margin
#define CAND_CAP 768
#define LISTCAP  1280

// ---------------- scratch (device globals; no allocations) ----------------
__device__ float          g_xc[BATCH * D_MODEL];            // exact fp32 (x_normed - b_post + b_pre)
__device__ __nv_bfloat16  g_xh[BATCH * D_MODEL];            // bf16 of xc
__device__ __nv_bfloat16  g_wh[(size_t)D_MODEL * N_FEAT];   // bf16 W_enc, [K,N] layout
__device__ float          g_wT[(size_t)N_FEAT * D_MODEL];   // fp32 W_enc^T, [N,K] for rescore
__device__ __nv_bfloat16  g_ench[(size_t)BATCH * N_FEAT];   // approx encodings (bf16)
__device__ int            g_candIdxA[BATCH * CAND_CAP];
__device__ int            g_candIdxD[BATCH * CAND_CAP];
__device__ float          g_candValA[BATCH * CAND_CAP];
__device__ float          g_candValD[BATCH * CAND_CAP];
__device__ int            g_candCntA[BATCH];
__device__ int            g_candCntD[BATCH];
__device__ float g_wAll[BATCH * TOPK];
__device__ int   g_iAll[BATCH * TOPK];
__device__ float g_wDead[BATCH * AUXK];
__device__ int   g_iDead[BATCH * AUXK];
__device__ float g_rowNum[BATCH];
__device__ float g_rowDen[BATCH];
__device__ int   g_deadAny;

// ---------------- helpers ----------------
__device__ __forceinline__ unsigned f2key(float f) {
    unsigned u = __float_as_uint(f);
    return (u & 0x80000000u) ? ~u : (u | 0x80000000u);   // order-preserving uint
}
__device__ __forceinline__ float key2f(unsigned k) {
    unsigned u = (k & 0x80000000u) ? (k ^ 0x80000000u) : ~k;
    return __uint_as_float(u);
}
__device__ __forceinline__ float bfbits2f(unsigned hbits) {
    return __uint_as_float(hbits << 16);
}
__device__ __forceinline__ void ldsm_x4(unsigned &r0, unsigned &r1, unsigned &r2, unsigned &r3,
                                        unsigned addr) {
    asm volatile("ldmatrix.sync.aligned.m8n8.x4.shared.b16 {%0,%1,%2,%3}, [%4];"
                 : "=r"(r0), "=r"(r1), "=r"(r2), "=r"(r3) : "r"(addr));
}
__device__ __forceinline__ void ldsm_x4_trans(unsigned &r0, unsigned &r1, unsigned &r2, unsigned &r3,
                                              unsigned addr) {
    asm volatile("ldmatrix.sync.aligned.m8n8.x4.trans.shared.b16 {%0,%1,%2,%3}, [%4];"
                 : "=r"(r0), "=r"(r1), "=r"(r2), "=r"(r3) : "r"(addr));
}

// ---------------- kernel 0: input prep (fp32 xc + bf16 copy) ----------------
__global__ void prep_kernel(const float* __restrict__ x,
                            const float* __restrict__ b_pre,
                            const float* __restrict__ b_post,
                            const float* __restrict__ avg) {
    int i = blockIdx.x * 256 + threadIdx.x;
    if (i < BATCH * D_MODEL) {
        float s = sqrtf((float)D_MODEL) / avg[0];
        int d = i % D_MODEL;
        float v = x[i] * s - b_post[d] + b_pre[d];
        g_xc[i] = v;
        g_xh[i] = __float2bfloat16(v);
    }
}

__global__ void deadany_kernel(const int* __restrict__ act) {
    __shared__ int f;
    if (threadIdx.x == 0) f = 0;
    __syncthreads();
    int loc = 0;
    for (int i = threadIdx.x; i < N_FEAT; i += 256)
        if (act[i] > DEAD_AFTER) loc = 1;
    if (loc) atomicOr(&f, 1);
    __syncthreads();
    if (threadIdx.x == 0) g_deadAny = f;
}

// ---------------- kernel 1: W_enc split (bf16) + transpose (fp32) ----------
__global__ __launch_bounds__(256) void wsplit_kernel(const float* __restrict__ W) {
    __shared__ float tile[32][33];
    int tx = threadIdx.x & 31, ty = threadIdx.x >> 5;
    int n0 = blockIdx.x * 32;
    int k0 = blockIdx.y * 32;
#pragma unroll
    for (int r = ty; r < 32; r += 8) {
        float v = W[(size_t)(k0 + r) * N_FEAT + n0 + tx];
        tile[r][tx] = v;
        g_wh[(size_t)(k0 + r) * N_FEAT + n0 + tx] = __float2bfloat16(v);
    }
    __syncthreads();
#pragma unroll
    for (int r = ty; r < 32; r += 8) {
        g_wT[(size_t)(n0 + r) * D_MODEL + k0 + tx] = tile[tx][r];
    }
}

// ---------------- kernel 2: bf16 GEMM (mma.sync m16n8k16 + ldmatrix) -------
// enc[1024,32768] = xh[1024,768] @ wh[768,32768], fp32 accum, bf16 out.
// CTA tile 128x128, 8 warps (4M x 2N), warp tile 32x64, BK=32, double-buffered.
__global__ __launch_bounds__(256) void gemm_kernel() {
    __shared__ __nv_bfloat16 As[2][128][40];     // [m][k], padded
    __shared__ __nv_bfloat16 Bs[2][32][136];     // [k][n], padded
    int tid = threadIdx.x;
    int warp = tid >> 5, lane = tid & 31;
    int mbase = (warp >> 1) * 32, nbase = (warp & 1) * 64;
    int bn = blockIdx.x, bm = blockIdx.y;

    const __nv_bfloat16* Ag = g_xh + (size_t)bm * 128 * D_MODEL;
    const __nv_bfloat16* Bg = g_wh + (size_t)bn * 128;

    int am0 = tid >> 2, ak = (tid & 3) * 8;
    int bk = tid >> 3, bn0 = (tid & 7) * 16;

    float acc[2][8][4];
#pragma unroll
    for (int mt = 0; mt < 2; mt++)
#pragma unroll
        for (int nt = 0; nt < 8; nt++)
#pragma unroll
            for (int q = 0; q < 4; q++) acc[mt][nt][q] = 0.f;

    uint4 pa0 = *(const uint4*)(Ag + (size_t)am0 * D_MODEL + ak);
    uint4 pa1 = *(const uint4*)(Ag + (size_t)(am0 + 64) * D_MODEL + ak);
    uint4 pb0 = *(const uint4*)(Bg + (size_t)bk * N_FEAT + bn0);
    uint4 pb1 = *(const uint4*)(Bg + (size_t)bk * N_FEAT + bn0 + 8);
    *(uint4*)(&As[0][am0][ak])      = pa0;
    *(uint4*)(&As[0][am0 + 64][ak]) = pa1;
    *(uint4*)(&Bs[0][bk][bn0])      = pb0;
    *(uint4*)(&Bs[0][bk][bn0 + 8])  = pb1;
    __syncthreads();

    // ldmatrix lane address components (constant across slabs)
    int lr = lane & 15;                 // row-within-16 for A, k-within-16 for B
    int hcol = (lane >> 4) << 3;        // 0 or 8: second half selector

    const int NSLAB = D_MODEL / 32;   // 24
    for (int s = 0; s < NSLAB; s++) {
        int cur = s & 1;
        if (s + 1 < NSLAB) {
            int k0 = (s + 1) * 32;
            pa0 = *(const uint4*)(Ag + (size_t)am0 * D_MODEL + k0 + ak);
            pa1 = *(const uint4*)(Ag + (size_t)(am0 + 64) * D_MODEL + k0 + ak);
            pb0 = *(const uint4*)(Bg + (size_t)(k0 + bk) * N_FEAT + bn0);
            pb1 = *(const uint4*)(Bg + (size_t)(k0 + bk) * N_FEAT + bn0 + 8);
        }
        unsigned aBase = (unsigned)__cvta_generic_to_shared(&As[cur][0][0]);
        unsigned bBase = (unsigned)__cvta_generic_to_shared(&Bs[cur][0][0]);
#pragma unroll
        for (int kk = 0; kk < 32; kk += 16) {
            // A fragments: one ldmatrix.x4 per 16x16 tile
            unsigned a[2][4];
#pragma unroll
            for (int mt = 0; mt < 2; mt++) {
                unsigned addr = aBase + (((mbase + mt * 16 + lr) * 40) + kk + hcol) * 2;
                ldsm_x4(a[mt][0], a[mt][1], a[mt][2], a[mt][3], addr);
            }
            // B fragments: ldmatrix.x4.trans serves two adjacent n8 tiles
            unsigned bfr[8][2];
#pragma unroll
            for (int j = 0; j < 4; j++) {
                unsigned addr = bBase + (((kk + lr) * 136) + nbase + j * 16 + hcol) * 2;
                unsigned r0, r1, r2, r3;
                ldsm_x4_trans(r0, r1, r2, r3, addr);
                bfr[2 * j][0] = r0; bfr[2 * j][1] = r1;
                bfr[2 * j + 1][0] = r2; bfr[2 * j + 1][1] = r3;
            }
#pragma unroll
            for (int nt = 0; nt < 8; nt++)
#pragma unroll
                for (int mt = 0; mt < 2; mt++) {
                    asm volatile(
                        "mma.sync.aligned.m16n8k16.row.col.f32.bf16.bf16.f32 "
                        "{%0,%1,%2,%3}, {%4,%5,%6,%7}, {%8,%9}, {%0,%1,%2,%3};"
                        : "+f"(acc[mt][nt][0]), "+f"(acc[mt][nt][1]),
                          "+f"(acc[mt][nt][2]), "+f"(acc[mt][nt][3])
                        : "r"(a[mt][0]), "r"(a[mt][1]), "r"(a[mt][2]), "r"(a[mt][3]),
                          "r"(bfr[nt][0]), "r"(bfr[nt][1]));
                }
        }
        __syncthreads();
        if (s + 1 < NSLAB) {
            int nxt = cur ^ 1;
            *(uint4*)(&As[nxt][am0][ak])      = pa0;
            *(uint4*)(&As[nxt][am0 + 64][ak]) = pa1;
            *(uint4*)(&Bs[nxt][bk][bn0])      = pb0;
            *(uint4*)(&Bs[nxt][bk][bn0 + 8])  = pb1;
            __syncthreads();
        }
    }

    int r = lane >> 2, cn = (lane & 3) * 2;
    __nv_bfloat16* C = g_ench + (size_t)(bm * 128) * N_FEAT + bn * 128;
#pragma unroll
    for (int mt = 0; mt < 2; mt++)
#pragma unroll
        for (int nt = 0; nt < 8; nt++) {
            int m0 = mbase + mt * 16 + r;
            int n0 = nbase + nt * 8 + cn;
            __nv_bfloat162 v0 = __float22bfloat162_rn(make_float2(acc[mt][nt][0], acc[mt][nt][1]));
            __nv_bfloat162 v1 = __float22bfloat162_rn(make_float2(acc[mt][nt][2], acc[mt][nt][3]));
            *(__nv_bfloat162*)&C[(size_t)m0 * N_FEAT + n0]       = v0;
            *(__nv_bfloat162*)&C[(size_t)(m0 + 8) * N_FEAT + n0] = v1;
        }
}

// ---------------- kernel 3: candidate extraction (both selections) ---------
__global__ __launch_bounds__(256) void cand_kernel(const int* __restrict__ act) {
    __shared__ unsigned histAD[4096];              // packed: A low16, D high16
    __shared__ unsigned listKeyA[LISTCAP]; __shared__ int listIdxA[LISTCAP];
    __shared__ unsigned listKeyD[LISTCAP]; __shared__ int listIdxD[LISTCAP];
    __shared__ int chs[256];
    __shared__ int s_binA, s_aboveA, s_binD, s_aboveD;
    __shared__ int s_cntA, s_cntD, s_mA, s_mD, s_subA, s_subD;

    int tid = threadIdx.x, row = blockIdx.x;
    const uint4* e8 = (const uint4*)(g_ench + (size_t)row * N_FEAT);   // 8 bf16 per uint4
    const int4* a4 = (const int4*)act;

    for (int i = tid; i < 4096; i += 256) histAD[i] = 0;
    if (tid == 0) { s_cntA = 0; s_cntD = 0; s_mA = 0; s_mD = 0; }
    __syncthreads();

    // pass 1: packed histogram
    for (int i = tid; i < N_FEAT / 8; i += 256) {
        uint4 v = e8[i]; int4 av0 = a4[2 * i], av1 = a4[2 * i + 1];
        unsigned hw[4] = {v.x, v.y, v.z, v.w};
        int aa[8] = {av0.x, av0.y, av0.z, av0.w, av1.x, av1.y, av1.z, av1.w};
#pragma unroll
        for (int j = 0; j < 8; j++) {
            unsigned hb = (j & 1) ? (hw[j >> 1] >> 16) : (hw[j >> 1] & 0xFFFFu);
            unsigned key = f2key(bfbits2f(hb));
            atomicAdd(&histAD[key >> 20], 1u + ((aa[j] > DEAD_AFTER) ? 0x10000u : 0u));
        }
    }
    __syncthreads();

    // thresholds: A (low halves)
    {
        int c0 = tid * 16; unsigned sA = 0;
#pragma unroll
        for (int j = 0; j < 16; j++) sA += histAD[c0 + j] & 0xFFFFu;
        chs[tid] = (int)sA;
        __syncthreads();
        if (tid == 0) {
            int cum = 0, bin = -1, above = 0;
            for (int ch = 255; ch >= 0; ch--) {
                if (cum + chs[ch] >= NEED_A) {
                    for (int b = ch * 16 + 15; b >= ch * 16; b--) {
                        int c = (int)(histAD[b] & 0xFFFFu);
                        if (cum + c >= NEED_A) { bin = b; above = cum; break; }
                        cum += c;
                    }
                    break;
                }
                cum += chs[ch];
            }
            if (bin < 0) above = cum;
            s_binA = bin; s_aboveA = above;
        }
        __syncthreads();
    }
    // thresholds: D (high halves)
    {
        int c0 = tid * 16; unsigned sD = 0;
#pragma unroll
        for (int j = 0; j < 16; j++) sD += histAD[c0 + j] >> 16;
        chs[tid] = (int)sD;
        __syncthreads();
        if (tid == 0) {
            int cum = 0, bin = -1, above = 0;
            for (int ch = 255; ch >= 0; ch--) {
                if (cum + chs[ch] >= NEED_D) {
                    for (int b = ch * 16 + 15; b >= ch * 16; b--) {
                        int c = (int)(histAD[b] >> 16);
                        if (cum + c >= NEED_D) { bin = b; above = cum; break; }
                        cum += c;
                    }
                    break;
                }
                cum += chs[ch];
            }
            if (bin < 0) above = cum;
            s_binD = bin; s_aboveD = above;
        }
        __syncthreads();
    }

    int binA = s_binA, binD = s_binD;

    // pass 2: emit above-bin directly; in-bin to smem lists
    for (int i = tid; i < N_FEAT / 8; i += 256) {
        uint4 v = e8[i]; int4 av0 = a4[2 * i], av1 = a4[2 * i + 1];
        unsigned hw[4] = {v.x, v.y, v.z, v.w};
        int aa[8] = {av0.x, av0.y, av0.z, av0.w, av1.x, av1.y, av1.z, av1.w};
#pragma unroll
        for (int j = 0; j < 8; j++) {
            int idx = i * 8 + j;
            unsigned hb = (j & 1) ? (hw[j >> 1] >> 16) : (hw[j >> 1] & 0xFFFFu);
            unsigned key = f2key(bfbits2f(hb));
            int b = (int)(key >> 20);
            if (binA < 0 || b > binA) {
                int p = atomicAdd(&s_cntA, 1);
                if (p < CAND_CAP) g_candIdxA[row * CAND_CAP + p] = idx;
            } else if (b == binA) {
                int p = atomicAdd(&s_mA, 1);
                if (p < LISTCAP) { listKeyA[p] = key; listIdxA[p] = idx; }
            }
            if (aa[j] > DEAD_AFTER) {
                if (binD < 0 || b > binD) {
                    int p = atomicAdd(&s_cntD, 1);
                    if (p < CAND_CAP) g_candIdxD[row * CAND_CAP + p] = idx;
                } else if (b == binD) {
                    int p = atomicAdd(&s_mD, 1);
                    if (p < LISTCAP) { listKeyD[p] = key; listIdxD[p] = idx; }
                }
            }
        }
    }
    __syncthreads();

    // sub-bin refinement (next 12 key bits)
    for (int i = tid; i < 4096; i += 256) histAD[i] = 0;
    __syncthreads();
    int mA = min(s_mA, LISTCAP), mD = min(s_mD, LISTCAP);
    for (int i = tid; i < mA; i += 256) atomicAdd(&histAD[(listKeyA[i] >> 8) & 0xFFF], 1u);
    for (int i = tid; i < mD; i += 256) atomicAdd(&histAD[(listKeyD[i] >> 8) & 0xFFF], 0x10000u);
    __syncthreads();
    if (tid == 0) {
        int need = NEED_A - s_aboveA, cum = 0, sub = 0;
        if (binA >= 0) {
            for (int b = 4095; b >= 0; b--) {
                cum += (int)(histAD[b] & 0xFFFFu);
                if (cum >= need) { sub = b; break; }
            }
        }
        s_subA = sub;
        need = NEED_D - s_aboveD; cum = 0; sub = 0;
        if (binD >= 0) {
            for (int b = 4095; b >= 0; b--) {
                cum += (int)(histAD[b] >> 16);
                if (cum >= need) { sub = b; break; }
            }
        }
        s_subD = sub;
    }
    __syncthreads();
    int subA = s_subA, subD = s_subD;
    for (int i = tid; i < mA; i += 256)
        if ((int)((listKeyA[i] >> 8) & 0xFFF) >= subA) {
            int p = atomicAdd(&s_cntA, 1);
            if (p < CAND_CAP) g_candIdxA[row * CAND_CAP + p] = listIdxA[i];
        }
    for (int i = tid; i < mD; i += 256)
        if ((int)((listKeyD[i] >> 8) & 0xFFF) >= subD) {
            int p = atomicAdd(&s_cntD, 1);
            if (p < CAND_CAP) g_candIdxD[row * CAND_CAP + p] = listIdxD[i];
        }
    __syncthreads();
    if (tid == 0) {
        g_candCntA[row] = min(s_cntA, CAND_CAP);
        g_candCntD[row] = min(s_cntD, CAND_CAP);
    }
}

// ---------------- kernel 4: exact fp32 rescore (warp per candidate) ---------
__global__ __launch_bounds__(256) void rescore_kernel() {
    __shared__ float xs[D_MODEL];
    int row = blockIdx.x, tid = threadIdx.x;
    int lane = tid & 31, warp = tid >> 5;
    for (int i = tid; i < D_MODEL; i += 256) xs[i] = g_xc[row * D_MODEL + i];
    __syncthreads();
    int cA = g_candCntA[row], cD = g_candCntD[row];
    int tot = cA + cD;
    const float4* x4 = (const float4*)xs;
    for (int t = warp; t < tot; t += 8) {
        int idx = (t < cA) ? g_candIdxA[row * CAND_CAP + t]
                           : g_candIdxD[row * CAND_CAP + (t - cA)];
        const float4* w4 = (const float4*)(g_wT + (size_t)idx * D_MODEL);
        float acc = 0.f;
#pragma unroll
        for (int i = 0; i < 6; i++) {
            float4 w = w4[lane + 32 * i], xv = x4[lane + 32 * i];
            acc += w.x * xv.x + w.y * xv.y + w.z * xv.z + w.w * xv.w;
        }
#pragma unroll
        for (int o = 16; o; o >>= 1) acc += __shfl_xor_sync(0xffffffffu, acc, o);
        if (lane == 0) {
            if (t < cA) g_candValA[row * CAND_CAP + t] = acc;
            else        g_candValD[row * CAND_CAP + (t - cA)] = acc;
        }
    }
}

// ---------------- kernel 5: final exact top-K among candidates --------------
__global__ __launch_bounds__(256) void select_kernel() {
    __shared__ unsigned long long sv[CAND_CAP];
    __shared__ unsigned long long wred[8];
    int row = blockIdx.x, tid = threadIdx.x;
    int isD = blockIdx.y;
    int cnt  = isD ? g_candCntD[row] : g_candCntA[row];
    int Ksel = isD ? AUXK : TOPK;
    const float* vals = isD ? &g_candValD[row * CAND_CAP] : &g_candValA[row * CAND_CAP];
    const int*   idxs = isD ? &g_candIdxD[row * CAND_CAP] : &g_candIdxA[row * CAND_CAP];
    float* outW = isD ? &g_wDead[row * AUXK] : &g_wAll[row * TOPK];
    int*   outI = isD ? &g_iDead[row * AUXK] : &g_iAll[row * TOPK];

    for (int i = tid; i < cnt; i += 256)
        sv[i] = ((unsigned long long)f2key(vals[i]) << 32) | (unsigned)(~(unsigned)idxs[i]);
    __syncthreads();

    int take = min(Ksel, cnt);
    for (int t = 0; t < take; t++) {
        unsigned long long best = 0;
        for (int i = tid; i < cnt; i += 256) if (sv[i] > best) best = sv[i];
#pragma unroll
        for (int o = 16; o; o >>= 1) {
            unsigned long long other = __shfl_xor_sync(0xffffffffu, best, o);
            if (other > best) best = other;
        }
        if ((tid & 31) == 0) wred[tid >> 5] = best;
        __syncthreads();
        if (tid < 8) {
            best = wred[tid];
#pragma unroll
            for (int o = 4; o; o >>= 1) {
                unsigned long long other = __shfl_xor_sync(0xffu, best, o);
                if (other > best) best = other;
            }
            if (tid == 0) wred[0] = best;
        }
        __syncthreads();
        unsigned long long b = wred[0];
        if (tid == 0) {
            outW[t] = key2f((unsigned)(b >> 32));
            outI[t] = (int)(~(unsigned)b);
        }
        for (int i = tid; i < cnt; i += 256) if (sv[i] == b) sv[i] = 0;
        __syncthreads();
    }
    for (int t = take + tid; t < Ksel; t += 256) { outW[t] = 0.f; outI[t] = 0; }
}

// ---------------- kernel 6: sparse decode + losses + output ----------------
__global__ __launch_bounds__(256) void decode_kernel(const float* __restrict__ x,
                                                     const float* __restrict__ Wdec,
                                                     const float* __restrict__ b_post,
                                                     const float* __restrict__ avg,
                                                     float* __restrict__ out,
                                                     int writeLoss) {
    int row = blockIdx.x, tid = threadIdx.x;
    __shared__ float sw[TOPK];  __shared__ int si[TOPK];
    __shared__ float swd[AUXK]; __shared__ int sid[AUXK];
    __shared__ float sred[256];

    if (tid < TOPK) { sw[tid] = g_wAll[row * TOPK + tid]; si[tid] = g_iAll[row * TOPK + tid]; }
    if (tid < AUXK) { swd[tid] = g_wDead[row * AUXK + tid]; sid[tid] = g_iDead[row * AUXK + tid]; }
    __syncthreads();

    float tgt = sqrtf((float)D_MODEL);
    float an  = avg[0];
    float sN = tgt / an;
    float sD = an / tgt;

    int d0 = tid, d1 = tid + 256, d2 = tid + 512;
    float y0 = 0.f, y1 = 0.f, y2 = 0.f;
    float a0 = 0.f, a1 = 0.f, a2 = 0.f;
#pragma unroll 4
    for (int k = 0; k < TOPK; k++) {
        const float* R = Wdec + (size_t)si[k] * D_MODEL;
        float w = sw[k];
        y0 += w * R[d0]; y1 += w * R[d1]; y2 += w * R[d2];
    }
#pragma unroll 4
    for (int k = 0; k < AUXK; k++) {
        const float* R = Wdec + (size_t)sid[k] * D_MODEL;
        float w = swd[k];
        a0 += w * R[d0]; a1 += w * R[d1]; a2 += w * R[d2];
    }

    float rec = 0.f, den = 0.f, aux = 0.f;
    {
        float xn = x[(size_t)row * D_MODEL + d0] * sN;
        float yn = y0 + b_post[d0];
        float df = xn - yn; rec += df * df; den += xn * xn;
        float t2 = (yn - xn) - a0; aux += t2 * t2;
        out[(size_t)row * D_MODEL + d0] = yn * sD;
    }
    {
        float xn = x[(size_t)row * D_MODEL + d1] * sN;
        float yn = y1 + b_post[d1];
        float df = xn - yn; rec += df * df; den += xn * xn;
        float t2 = (yn - xn) - a1; aux += t2 * t2;
        out[(size_t)row * D_MODEL + d1] = yn * sD;
    }
    {
        float xn = x[(size_t)row * D_MODEL + d2] * sN;
        float yn = y2 + b_post[d2];
        float df = xn - yn; rec += df * df; den += xn * xn;
        float t2 = (yn - xn) - a2; aux += t2 * t2;
        out[(size_t)row * D_MODEL + d2] = yn * sD;
    }

    sred[tid] = rec; __syncthreads();
    for (int s = 128; s > 0; s >>= 1) { if (tid < s) sred[tid] += sred[tid + s]; __syncthreads(); }
    float recTot = sred[0]; __syncthreads();
    sred[tid] = den; __syncthreads();
    for (int s = 128; s > 0; s >>= 1) { if (tid < s) sred[tid] += sred[tid + s]; __syncthreads(); }
    float denTot = sred[0]; __syncthreads();
    sred[tid] = aux; __syncthreads();
    for (int s = 128; s > 0; s >>= 1) { if (tid < s) sred[tid] += sred[tid + s]; __syncthreads(); }
    float auxTot = sred[0];

    if (tid == 0) {
        float lrec = recTot / (float)D_MODEL;
        float laux = g_deadAny ? (auxTot / (float)D_MODEL) : 0.f;
        if (writeLoss)
            out[(size_t)BATCH * D_MODEL + row] = lrec + AUX_COEFF * laux;
        g_rowNum[row] = recTot;
        g_rowDen[row] = denTot;
    }
}

// ---------------- kernel 7: fvu ----------------
__global__ __launch_bounds__(256) void fvu_kernel(float* __restrict__ out, int fvuIdx) {
    __shared__ float sn[256], sd[256];
    int tid = threadIdx.x;
    float n = 0.f, d = 0.f;
    for (int i = tid; i < BATCH; i += 256) { n += g_rowNum[i]; d += g_rowDen[i]; }
    sn[tid] = n; sd[tid] = d;
    __syncthreads();
    for (int s = 128; s > 0; s >>= 1) {
        if (tid < s) { sn[tid] += sn[tid + s]; sd[tid] += sd[tid + s]; }
        __syncthreads();
    }
    if (tid == 0 && fvuIdx >= 0) out[fvuIdx] = sn[0] / sd[0];
}

// ---------------- launcher ----------------
extern "C" void kernel_launch(void* const* d_in, const int* in_sizes, int n_in,
                              void* d_out, int out_size) {
    const float *x = 0, *W_enc = 0, *W_dec = 0, *b_pre = 0, *b_post = 0, *avg = 0;
    const int* act = 0;
    int nBig = 0, nBias = 0;
    for (int i = 0; i < n_in; i++) {
        long s = in_sizes[i];
        if (s == (long)D_MODEL * N_FEAT) {
            if (nBig++ == 0) W_enc = (const float*)d_in[i];
            else             W_dec = (const float*)d_in[i];
        } else if (s == (long)BATCH * D_MODEL) {
            x = (const float*)d_in[i];
        } else if (s == D_MODEL) {
            if (nBias++ == 0) b_pre = (const float*)d_in[i];
            else              b_post = (const float*)d_in[i];
        } else if (s == 1) {
            avg = (const float*)d_in[i];
        } else if (s == N_FEAT) {
            act = (const int*)d_in[i];
        }
    }
    float* out = (float*)d_out;

    int writeLoss = (out_size >= BATCH * D_MODEL + BATCH) ? 1 : 0;
    int fvuIdx = (out_size >= BATCH * D_MODEL + BATCH + 1) ? (BATCH * D_MODEL + BATCH) : -1;

    prep_kernel<<<(BATCH * D_MODEL + 255) / 256, 256>>>(x, b_pre, b_post, avg);
    wsplit_kernel<<<dim3(N_FEAT / 32, D_MODEL / 32), 256>>>(W_enc);
    deadany_kernel<<<1, 256>>>(act);

    gemm_kernel<<<dim3(N_FEAT / 128, BATCH / 128), 256>>>();

    cand_kernel<<<BATCH, 256>>>(act);
    rescore_kernel<<<BATCH, 256>>>();
    select_kernel<<<dim3(BATCH, 2), 256>>>();

    decode_kernel<<<BATCH, 256>>>(x, W_dec, b_post, avg, out, writeLoss);
    if (fvuIdx >= 0) fvu_kernel<<<1, 256>>>(out, fvuIdx);
}